// round 15
// baseline (speedup 1.0000x reference)
#include <cuda_runtime.h>
#include <cuda_bf16.h>
#include <cuda_fp16.h>
#include <math.h>

typedef unsigned long long u64;
typedef unsigned int u32;

#define BATCH 16384
#define HALF  8192
#define NF 10
#define LL 20
#define DD 16
#define FEAT 160
#define NE 8
#define SS 64
#define NG 3
#define TT 32
#define NCOLS (NE*SS)

// ---- expert tiling: 128x128, full K=160 resident (5 chunks of 32) ----
#define TM 128
#define TN 128
#define SSTRIDE 40
#define STILE_U16 (128 * SSTRIDE)
#define DYN_E (10 * STILE_U16 * 2)      // 102400 B

// Scratch (device globals: no allocation allowed)
__device__ __align__(16) unsigned short g_xhi[BATCH * FEAT];
__device__ __align__(16) unsigned short g_xlo[BATCH * FEAT];
__device__ __align__(16) unsigned short g_whi[NCOLS * FEAT];
__device__ __align__(16) unsigned short g_ghi[32 * FEAT];
__device__ __align__(16) unsigned short g_glo[32 * FEAT];
__device__ __align__(16) float          g_gate[BATCH * 32];
__device__ __align__(16) __half         g_exp[BATCH * NCOLS];

// ---------------- helpers ----------------
__device__ __forceinline__ u64 pack2(float lo, float hi) {
    u64 d;
    asm("mov.b64 %0, {%1, %2};" : "=l"(d)
        : "r"(__float_as_uint(lo)), "r"(__float_as_uint(hi)));
    return d;
}
__device__ __forceinline__ void unpack2(u64 v, float &lo, float &hi) {
    unsigned a, b;
    asm("mov.b64 {%0, %1}, %2;" : "=r"(a), "=r"(b) : "l"(v));
    lo = __uint_as_float(a); hi = __uint_as_float(b);
}
__device__ __forceinline__ u64 ffma2(u64 a, u64 b, u64 c) {
    u64 d;
    asm("fma.rn.f32x2 %0, %1, %2, %3;" : "=l"(d) : "l"(a), "l"(b), "l"(c));
    return d;
}
__device__ __forceinline__ u32 smem_u32(const void* p) {
    u32 a;
    asm("{ .reg .u64 t; cvta.to.shared.u64 t, %1; cvt.u32.u64 %0, t; }" : "=r"(a) : "l"(p));
    return a;
}
__device__ __forceinline__ void ldsm4(u32 addr, u32 &r0, u32 &r1, u32 &r2, u32 &r3) {
    asm volatile("ldmatrix.sync.aligned.m8n8.x4.shared.b16 {%0,%1,%2,%3}, [%4];"
                 : "=r"(r0), "=r"(r1), "=r"(r2), "=r"(r3) : "r"(addr));
}
__device__ __forceinline__ void mma16816(float* d, const u32* a, const u32* b) {
    asm volatile("mma.sync.aligned.m16n8k16.row.col.f32.bf16.bf16.f32 "
                 "{%0,%1,%2,%3}, {%4,%5,%6,%7}, {%8,%9}, {%0,%1,%2,%3};"
                 : "+f"(d[0]), "+f"(d[1]), "+f"(d[2]), "+f"(d[3])
                 : "r"(a[0]), "r"(a[1]), "r"(a[2]), "r"(a[3]), "r"(b[0]), "r"(b[1]));
}
#define CP16(dst, src) \
    asm volatile("cp.async.cg.shared.global [%0], [%1], 16;" :: "r"(dst), "l"(src) : "memory")
#define CP_COMMIT() asm volatile("cp.async.commit_group;" ::: "memory")
#define CP_WAIT1()  asm volatile("cp.async.wait_group 1;" ::: "memory")
#define CP_WAIT0()  asm volatile("cp.async.wait_group 0;" ::: "memory")

// ---------------------------------------------------------------------------
// Kernel A: embedding gather + sum for one batch half (+ weight prep on h0).
// ---------------------------------------------------------------------------
__global__ __launch_bounds__(256) void gather_kernel(const int* __restrict__ ids32,
                                                     const float4* __restrict__ emb,
                                                     const float* __restrict__ ew,
                                                     const float* __restrict__ gwp,
                                                     int b_off) {
    if (blockIdx.x >= (NF * HALF) / 64) {
        int wpidx = (blockIdx.x - (NF * HALF) / 64) * 256 + threadIdx.x;
        if (wpidx < NCOLS * FEAT) {
            int c = wpidx & (NCOLS - 1);
            int k = wpidx >> 9;
            int e = c >> 6, s = c & 63;
            float w = ew[((long)e * FEAT + k) * SS + s];
            __nv_bfloat16 h = __float2bfloat16_rn(w);
            g_whi[(long)c * FEAT + k] = *(unsigned short*)&h;
        } else if (wpidx < NCOLS * FEAT + 32 * FEAT) {
            int gidx = wpidx - NCOLS * FEAT;
            int c = gidx & 31;
            int k = gidx >> 5;
            float w = 0.f;
            if (c < 24) {
                int g = c >> 3, e = c & 7;
                w = gwp[((long)g * FEAT + k) * NE + e];
            }
            __nv_bfloat16 h = __float2bfloat16_rn(w);
            float r = w - __bfloat162float(h);
            __nv_bfloat16 l = __float2bfloat16_rn(r);
            g_ghi[(long)c * FEAT + k] = *(unsigned short*)&h;
            g_glo[(long)c * FEAT + k] = *(unsigned short*)&l;
        }
        return;
    }

    __shared__ int s_is64;
    if (threadIdx.x == 0) {
        const unsigned* w = (const unsigned*)ids32;
        s_is64 = (w[1] == 0u && w[3] == 0u && w[5] == 0u && w[7] == 0u) ? 1 : 0;
    }
    __syncthreads();
    const int is64 = s_is64;

    int tid  = threadIdx.x;
    int pp   = blockIdx.x * 64 + (tid >> 2);   // 0 .. NF*HALF-1
    int lane = tid & 3;
    int f = pp >> 13;
    int b = b_off + (pp & (HALF - 1));
    long base = ((long)f * BATCH + b) * LL;

    float4 acc = make_float4(0.f, 0.f, 0.f, 0.f);
    if (is64) {
        const ulonglong2* idv = (const ulonglong2*)(ids32 + 2 * base);
        #pragma unroll
        for (int l2 = 0; l2 < 10; l2++) {
            ulonglong2 two = __ldcs(&idv[l2]);
            int id0 = (int)two.x;
            int id1 = (int)two.y;
            float4 v0 = __ldg(&emb[(long)id0 * 4 + lane]);
            float4 v1 = __ldg(&emb[(long)id1 * 4 + lane]);
            acc.x += v0.x + v1.x; acc.y += v0.y + v1.y;
            acc.z += v0.z + v1.z; acc.w += v0.w + v1.w;
        }
    } else {
        const int4* idv = (const int4*)(ids32 + base);
        #pragma unroll
        for (int l4 = 0; l4 < 5; l4++) {
            int4 four = __ldcs(&idv[l4]);
            float4 v0 = __ldg(&emb[(long)four.x * 4 + lane]);
            float4 v1 = __ldg(&emb[(long)four.y * 4 + lane]);
            float4 v2 = __ldg(&emb[(long)four.z * 4 + lane]);
            float4 v3 = __ldg(&emb[(long)four.w * 4 + lane]);
            acc.x += (v0.x + v1.x) + (v2.x + v3.x);
            acc.y += (v0.y + v1.y) + (v2.y + v3.y);
            acc.z += (v0.z + v1.z) + (v2.z + v3.z);
            acc.w += (v0.w + v1.w) + (v2.w + v3.w);
        }
    }
    int fb = f * DD + lane * 4;
    long xoff = (long)b * FEAT + fb;

    float vals[4] = {acc.x, acc.y, acc.z, acc.w};
    unsigned short hi[4], lo[4];
    #pragma unroll
    for (int j = 0; j < 4; j++) {
        __nv_bfloat16 h = __float2bfloat16_rn(vals[j]);
        float r = vals[j] - __bfloat162float(h);
        __nv_bfloat16 l = __float2bfloat16_rn(r);
        hi[j] = *(unsigned short*)&h;
        lo[j] = *(unsigned short*)&l;
    }
    *(uint2*)&g_xhi[xoff] = make_uint2((u32)hi[0] | ((u32)hi[1] << 16),
                                       (u32)hi[2] | ((u32)hi[3] << 16));
    *(uint2*)&g_xlo[xoff] = make_uint2((u32)lo[0] | ((u32)lo[1] << 16),
                                       (u32)lo[2] | ((u32)lo[3] << 16));
}

// ---------------------------------------------------------------------------
// Kernel B: experts GEMM (1-term bf16, full-K-resident) + gates GEMM
// (3-term, staged, blockIdx.y==4). Operates on one batch half via b_off.
// ---------------------------------------------------------------------------
__device__ __forceinline__ void fill_gate_stage(u32 smb, int stage, int ks,
                                                int b0, int tid) {
    int k0 = ks * 32;
    #pragma unroll
    for (int it = 0; it < 5; it++) {
        int idx = tid + it * 256;
        if (idx < 1024) {
            int tile = idx >> 9;
            int r    = (idx >> 2) & 127;
            int ch   = idx & 3;
            u32 dst = smb + (u32)(((stage * 3 + tile) * STILE_U16 + r * SSTRIDE + ch * 8) * 2);
            const unsigned short* src = (tile == 0)
                ? &g_xhi[(long)(b0 + r) * FEAT + k0 + ch * 8]
                : &g_xlo[(long)(b0 + r) * FEAT + k0 + ch * 8];
            CP16(dst, src);
        } else {
            int idx2 = idx - 1024;
            int half = idx2 >> 7;
            int r    = (idx2 >> 2) & 31;
            int ch   = idx2 & 3;
            u32 dst = smb + (u32)(((stage * 3 + 2) * STILE_U16
                                   + (half * 32 + r) * SSTRIDE + ch * 8) * 2);
            const unsigned short* src = half
                ? &g_glo[(long)r * FEAT + k0 + ch * 8]
                : &g_ghi[(long)r * FEAT + k0 + ch * 8];
            CP16(dst, src);
        }
    }
}

__global__ void __launch_bounds__(256, 2) expert_mma_kernel(const float* __restrict__ eb,
                                                            const float* __restrict__ gb,
                                                            int b_off) {
    extern __shared__ unsigned short sm16[];
    __shared__ float s_bias[TN];

    int tid  = threadIdx.x;
    int wid  = tid >> 5;
    int lane = tid & 31;
    int b0   = b_off + blockIdx.x * TM;

    u32 smb = smem_u32(sm16);

    if (blockIdx.y == 4) {
        if (tid < 32) s_bias[tid] = (tid < 24) ? gb[tid] : 0.f;

        fill_gate_stage(smb, 0, 0, b0, tid); CP_COMMIT();
        fill_gate_stage(smb, 1, 1, b0, tid); CP_COMMIT();

        int m0 = wid * 16;
        u32 aOff = (u32)((m0 + (lane & 15)) * SSTRIDE + ((lane & 16) ? 8 : 0)) * 2;
        u32 bOff = (u32)(((lane & 7) + ((lane & 16) ? 8 : 0)) * SSTRIDE + ((lane & 8) ? 8 : 0)) * 2;

        float acc[4][4];
        #pragma unroll
        for (int nt = 0; nt < 4; nt++)
            #pragma unroll
            for (int q = 0; q < 4; q++) acc[nt][q] = 0.f;

        #pragma unroll 1
        for (int ks = 0; ks < 5; ks++) {
            if (ks < 4) CP_WAIT1(); else CP_WAIT0();
            __syncthreads();

            int stage = ks & 1;
            u32 aHiB = smb + (u32)((stage * 3 + 0) * STILE_U16 * 2) + aOff;
            u32 aLoB = smb + (u32)((stage * 3 + 1) * STILE_U16 * 2) + aOff;
            u32 bHiB = smb + (u32)((stage * 3 + 2) * STILE_U16 * 2) + bOff;
            u32 bLoB = bHiB + (u32)(32 * SSTRIDE * 2);

            #pragma unroll
            for (int kk = 0; kk < 2; kk++) {
                u32 kb = (u32)(kk * 32);
                u32 ah[4], al[4];
                ldsm4(aHiB + kb, ah[0], ah[1], ah[2], ah[3]);
                ldsm4(aLoB + kb, al[0], al[1], al[2], al[3]);
                u32 bh[2][4], blo[2][4];
                #pragma unroll
                for (int nt2 = 0; nt2 < 2; nt2++) {
                    u32 noff = (u32)(nt2 * 16 * SSTRIDE * 2);
                    ldsm4(bHiB + noff + kb, bh[nt2][0], bh[nt2][1], bh[nt2][2], bh[nt2][3]);
                    ldsm4(bLoB + noff + kb, blo[nt2][0], blo[nt2][1], blo[nt2][2], blo[nt2][3]);
                }
                #pragma unroll
                for (int nt2 = 0; nt2 < 2; nt2++) {
                    mma16816(acc[2 * nt2],     ah, &bh[nt2][0]);
                    mma16816(acc[2 * nt2 + 1], ah, &bh[nt2][2]);
                    mma16816(acc[2 * nt2],     ah, &blo[nt2][0]);
                    mma16816(acc[2 * nt2 + 1], ah, &blo[nt2][2]);
                    mma16816(acc[2 * nt2],     al, &bh[nt2][0]);
                    mma16816(acc[2 * nt2 + 1], al, &bh[nt2][2]);
                }
            }

            __syncthreads();
            if (ks + 2 < 5) { fill_gate_stage(smb, ks & 1, ks + 2, b0, tid); CP_COMMIT(); }
        }

        int r0 = b0 + m0 + (lane >> 2);
        #pragma unroll
        for (int nt = 0; nt < 3; nt++) {
            int cl = nt * 8 + (lane & 3) * 2;
            float bi0 = s_bias[cl], bi1 = s_bias[cl + 1];
            g_gate[(long)r0 * 32 + cl]           = acc[nt][0] + bi0;
            g_gate[(long)r0 * 32 + cl + 1]       = acc[nt][1] + bi1;
            g_gate[(long)(r0 + 8) * 32 + cl]     = acc[nt][2] + bi0;
            g_gate[(long)(r0 + 8) * 32 + cl + 1] = acc[nt][3] + bi1;
        }
        return;
    }

    // ---- experts path: 1-term bf16, full K resident ----
    int c0 = blockIdx.y * TN;
    if (tid < TN) {
        int c = c0 + tid;
        s_bias[tid] = eb[(c >> 6) * SS + (c & 63)];
    }

    #pragma unroll
    for (int it = 0; it < 20; it++) {
        int idx  = tid + it * 256;
        int half = idx >= 2560;
        int rem  = half ? idx - 2560 : idx;
        int c    = rem >> 9;
        int sub  = rem & 511;
        int r    = sub >> 2;
        int ch   = sub & 3;
        int k0   = c * 32;
        u32 dst = smb + (u32)(((half * 5 + c) * STILE_U16 + r * SSTRIDE + ch * 8) * 2);
        const unsigned short* src = half
            ? &g_whi[(long)(c0 + r) * FEAT + k0 + ch * 8]
            : &g_xhi[(long)(b0 + r) * FEAT + k0 + ch * 8];
        CP16(dst, src);
    }
    CP_COMMIT();
    CP_WAIT0();
    __syncthreads();

    int m0 = (wid >> 1) * 32;
    int n0 = (wid & 1) * 64;

    u32 aOff = (u32)((m0 + (lane & 15)) * SSTRIDE + ((lane & 16) ? 8 : 0)) * 2;
    u32 bOff = (u32)((n0 + (lane & 7) + ((lane & 16) ? 8 : 0)) * SSTRIDE + ((lane & 8) ? 8 : 0)) * 2;

    float acc[2][8][4];
    #pragma unroll
    for (int mt = 0; mt < 2; mt++)
        #pragma unroll
        for (int nt = 0; nt < 8; nt++)
            #pragma unroll
            for (int q = 0; q < 4; q++) acc[mt][nt][q] = 0.f;

    #pragma unroll
    for (int c = 0; c < 5; c++) {
        u32 aHiB = smb + (u32)(c * STILE_U16 * 2) + aOff;
        u32 bHiB = smb + (u32)((5 + c) * STILE_U16 * 2) + bOff;

        #pragma unroll
        for (int kk = 0; kk < 2; kk++) {
            u32 kb = (u32)(kk * 32);

            u32 ah[2][4];
            #pragma unroll
            for (int mt = 0; mt < 2; mt++) {
                u32 moff = (u32)(mt * 16 * SSTRIDE * 2);
                ldsm4(aHiB + moff + kb, ah[mt][0], ah[mt][1], ah[mt][2], ah[mt][3]);
            }
            u32 bh[4][4];
            #pragma unroll
            for (int nt2 = 0; nt2 < 4; nt2++) {
                u32 noff = (u32)(nt2 * 16 * SSTRIDE * 2);
                ldsm4(bHiB + noff + kb, bh[nt2][0], bh[nt2][1], bh[nt2][2], bh[nt2][3]);
            }

            #pragma unroll
            for (int mt = 0; mt < 2; mt++) {
                #pragma unroll
                for (int nt2 = 0; nt2 < 4; nt2++) {
                    mma16816(acc[mt][2 * nt2],     ah[mt], &bh[nt2][0]);
                    mma16816(acc[mt][2 * nt2 + 1], ah[mt], &bh[nt2][2]);
                }
            }
        }
    }

    #pragma unroll
    for (int mt = 0; mt < 2; mt++) {
        int row = b0 + m0 + mt * 16 + (lane >> 2);
        #pragma unroll
        for (int nt = 0; nt < 8; nt++) {
            int cl = n0 + nt * 8 + (lane & 3) * 2;
            float bi0 = s_bias[cl], bi1 = s_bias[cl + 1];
            float* d = acc[mt][nt];
            *(__half2*)&g_exp[(long)row * NCOLS + c0 + cl] =
                __floats2half2_rn(fmaxf(d[0] + bi0, 0.f), fmaxf(d[1] + bi1, 0.f));
            *(__half2*)&g_exp[(long)(row + 8) * NCOLS + c0 + cl] =
                __floats2half2_rn(fmaxf(d[2] + bi0, 0.f), fmaxf(d[3] + bi1, 0.f));
        }
    }
}

// ---------------------------------------------------------------------------
// Kernel C: head, full batch, warp-per-2-rows, 4 row-pair iterations (R13).
// ---------------------------------------------------------------------------
struct HeadSmem {
    ulonglong2 tw4[16][96];
    float mix[8][2][192];
    float ow0[NG * TT];
    float ow1[NG * TT];
    float tb[NG * TT];
    float ob[8];
};

__global__ __launch_bounds__(256) void head_kernel(const float* __restrict__ tw,
                                                   const float* __restrict__ tb,
                                                   const float* __restrict__ ow,
                                                   const float* __restrict__ ob,
                                                   float* __restrict__ out) {
    extern __shared__ char smem_raw[];
    HeadSmem* sm = (HeadSmem*)smem_raw;

    int tid  = threadIdx.x;
    int warp = tid >> 5;
    int lane = tid & 31;

    for (int i = tid; i < 16 * 96; i += 256) {
        int sp2 = i / 96, j = i % 96;
        int g = j >> 5, t = j & 31;
        int s0 = 4 * sp2;
        float v0 = tw[((long)g * SS + s0 + 0) * TT + t];
        float v1 = tw[((long)g * SS + s0 + 1) * TT + t];
        float v2 = tw[((long)g * SS + s0 + 2) * TT + t];
        float v3 = tw[((long)g * SS + s0 + 3) * TT + t];
        ulonglong2 v;
        v.x = pack2(v0, v1);
        v.y = pack2(v2, v3);
        sm->tw4[sp2][j] = v;
    }
    for (int i = tid; i < NG * TT; i += 256) {
        sm->ow0[i] = ow[i * 2 + 0];
        sm->ow1[i] = ow[i * 2 + 1];
        sm->tb[i]  = tb[i];
    }
    if (tid < NG * 2) sm->ob[tid] = ob[tid];
    __syncthreads();

    #pragma unroll 1
    for (int it = 0; it < 4; it++) {
        int bA = blockIdx.x * 8 + warp + it * 2048;
        int bB = bA + 8192;

        __syncwarp();

        int oSafe = (lane < 24) ? lane : 0;
        float lgA = g_gate[(long)bA * 32 + oSafe];
        float lgB = g_gate[(long)bB * 32 + oSafe];
        float gvA, gvB;
        {
            float mA = lgA, mB = lgB;
            #pragma unroll
            for (int b = 1; b <= 4; b <<= 1) {
                mA = fmaxf(mA, __shfl_xor_sync(0xFFFFFFFFu, mA, b));
                mB = fmaxf(mB, __shfl_xor_sync(0xFFFFFFFFu, mB, b));
            }
            float eA = __expf(lgA - mA);
            float eB = __expf(lgB - mB);
            float sA = eA, sB = eB;
            #pragma unroll
            for (int b = 1; b <= 4; b <<= 1) {
                sA += __shfl_xor_sync(0xFFFFFFFFu, sA, b);
                sB += __shfl_xor_sync(0xFFFFFFFFu, sB, b);
            }
            gvA = eA * __fdividef(1.f, sA);
            gvB = eB * __fdividef(1.f, sB);
        }
        float gtA[24], gtB[24];
        #pragma unroll
        for (int o = 0; o < 24; o++) {
            gtA[o] = __shfl_sync(0xFFFFFFFFu, gvA, o);
            gtB[o] = __shfl_sync(0xFFFFFFFFu, gvB, o);
        }

        const __half2* erA = (const __half2*)&g_exp[(long)bA * NCOLS];
        const __half2* erB = (const __half2*)&g_exp[(long)bB * NCOLS];
        #pragma unroll
        for (int g = 0; g < NG; g++) {
            float vA0 = 0.f, vA1 = 0.f, vB0 = 0.f, vB1 = 0.f;
            #pragma unroll
            for (int e = 0; e < NE; e++) {
                float2 fa = __half22float2(erA[e * (SS / 2) + lane]);
                float2 fb = __half22float2(erB[e * (SS / 2) + lane]);
                float ga = gtA[g * 8 + e], gbv = gtB[g * 8 + e];
                vA0 = fmaf(ga, fa.x, vA0);
                vA1 = fmaf(ga, fa.y, vA1);
                vB0 = fmaf(gbv, fb.x, vB0);
                vB1 = fmaf(gbv, fb.y, vB1);
            }
            *(float2*)&sm->mix[warp][0][g * SS + 2 * lane] = make_float2(vA0, vA1);
            *(float2*)&sm->mix[warp][1][g * SS + 2 * lane] = make_float2(vB0, vB1);
        }
        __syncwarp();

        float towA[NG], towB[NG];
        #pragma unroll
        for (int g = 0; g < NG; g++) {
            u64 accA = 0ull, accB = 0ull;
            const ulonglong2* mA = (const ulonglong2*)&sm->mix[warp][0][g * SS];
            const ulonglong2* mB = (const ulonglong2*)&sm->mix[warp][1][g * SS];
            #pragma unroll
            for (int sp2 = 0; sp2 < 16; sp2++) {
                ulonglong2 w  = sm->tw4[sp2][g * 32 + lane];
                ulonglong2 ma = mA[sp2];
                ulonglong2 mb = mB[sp2];
                accA = ffma2(ma.x, w.x, accA);
                accA = ffma2(ma.y, w.y, accA);
                accB = ffma2(mb.x, w.x, accB);
                accB = ffma2(mb.y, w.y, accB);
            }
            float l0, h0, l1, h1;
            unpack2(accA, l0, h0);
            unpack2(accB, l1, h1);
            float bias = sm->tb[g * TT + lane];
            towA[g] = fmaxf(l0 + h0 + bias, 0.f);
            towB[g] = fmaxf(l1 + h1 + bias, 0.f);
        }

        float lA[6], lB[6];
        #pragma unroll
        for (int g = 0; g < NG; g++) {
            lA[g * 2 + 0] = towA[g] * sm->ow0[g * TT + lane];
            lA[g * 2 + 1] = towA[g] * sm->ow1[g * TT + lane];
            lB[g * 2 + 0] = towB[g] * sm->ow0[g * TT + lane];
            lB[g * 2 + 1] = towB[g] * sm->ow1[g * TT + lane];
        }
        #pragma unroll
        for (int off = 16; off > 0; off >>= 1) {
            #pragma unroll
            for (int o = 0; o < 6; o++) {
                lA[o] += __shfl_xor_sync(0xFFFFFFFFu, lA[o], off);
                lB[o] += __shfl_xor_sync(0xFFFFFFFFu, lB[o], off);
            }
        }

        if (lane < 2) {
            const float* l = (lane == 0) ? lA : lB;
            int b = (lane == 0) ? bA : bB;
            float probs[6];
            #pragma unroll
            for (int g = 0; g < NG; g++) {
                float l0 = l[g * 2 + 0] + sm->ob[g * 2 + 0];
                float l1 = l[g * 2 + 1] + sm->ob[g * 2 + 1];
                float mm = fmaxf(l0, l1);
                float e0 = __expf(l0 - mm), e1 = __expf(l1 - mm);
                float inv = __fdividef(1.f, e0 + e1);
                probs[g * 2 + 0] = fminf(fmaxf(e0 * inv, 1e-15f), 1.f - 1e-15f);
                probs[g * 2 + 1] = fminf(fmaxf(e1 * inv, 1e-15f), 1.f - 1e-15f);
            }
            float cc = probs[1] * probs[3];
            float* o = out + (long)b * 10;
            o[0] = probs[0]; o[1] = probs[1]; o[2] = probs[1];
            o[3] = probs[2]; o[4] = probs[3]; o[5] = probs[3];
            o[6] = 1.f - cc; o[7] = cc; o[8] = cc;
            o[9] = probs[5];
        }
    }
}

extern "C" void kernel_launch(void* const* d_in, const int* in_sizes, int n_in,
                              void* d_out, int out_size) {
    const int*   ids = (const int*)d_in[0];
    const float* emb = (const float*)d_in[1];
    const float* ew  = (const float*)d_in[2];
    const float* eb  = (const float*)d_in[3];
    const float* gw  = (const float*)d_in[4];
    const float* gb  = (const float*)d_in[5];
    const float* tw  = (const float*)d_in[6];
    const float* tb  = (const float*)d_in[7];
    const float* ow  = (const float*)d_in[8];
    const float* ob  = (const float*)d_in[9];
    float* out = (float*)d_out;

    cudaFuncSetAttribute(expert_mma_kernel, cudaFuncAttributeMaxDynamicSharedMemorySize, DYN_E);
    cudaFuncSetAttribute(head_kernel, cudaFuncAttributeMaxDynamicSharedMemorySize,
                         (int)sizeof(HeadSmem));

    // Fresh side stream + events each call (host objects, not device memory).
    cudaStream_t s1;
    cudaStreamCreateWithFlags(&s1, cudaStreamNonBlocking);
    cudaEvent_t evG0, evE0;
    cudaEventCreateWithFlags(&evG0, cudaEventDisableTiming);
    cudaEventCreateWithFlags(&evE0, cudaEventDisableTiming);

    const int GMAIN = (NF * HALF) / 64;   // 1280

    // main: gather half 0 (+ weight prep)
    gather_kernel<<<GMAIN + 340, 256>>>(ids, (const float4*)emb, ew, gw, 0);
    cudaEventRecord(evG0, 0);

    // side: expert half 0 overlaps gather half 1
    cudaStreamWaitEvent(s1, evG0, 0);
    expert_mma_kernel<<<dim3(HALF / TM, 5), 256, DYN_E, s1>>>(eb, gb, 0);
    cudaEventRecord(evE0, s1);

    // main: gather half 1, then expert half 1 (in-order), then join + head
    gather_kernel<<<GMAIN, 256>>>(ids, (const float4*)emb, ew, gw, HALF);
    expert_mma_kernel<<<dim3(HALF / TM, 5), 256, DYN_E>>>(eb, gb, HALF);
    cudaStreamWaitEvent(0, evE0, 0);
    head_kernel<<<256, 256, sizeof(HeadSmem)>>>(tw, tb, ow, ob, out);
}

// round 16
// speedup vs baseline: 1.3640x; 1.3640x over previous
#include <cuda_runtime.h>
#include <cuda_bf16.h>
#include <cuda_fp16.h>
#include <math.h>

typedef unsigned long long u64;
typedef unsigned int u32;

#define BATCH 16384
#define NF 10
#define LL 20
#define DD 16
#define FEAT 160
#define NE 8
#define SS 64
#define NG 3
#define TT 32
#define NCOLS (NE*SS)

// ---- expert tiling: 128x128, full K=160 resident (5 chunks of 32) ----
#define TM 128
#define TN 128
#define SSTRIDE 40
#define STILE_U16 (128 * SSTRIDE)       // one 32-k chunk tile: 10240 B
#define DYN_E (10 * STILE_U16 * 2)      // 102400 B: xhi[5 chunks] + whi[5 chunks]

// Scratch (device globals: no allocation allowed)
__device__ __align__(16) unsigned short g_xhi[BATCH * FEAT];
__device__ __align__(16) unsigned short g_xlo[BATCH * FEAT];
__device__ __align__(16) unsigned short g_whi[NCOLS * FEAT];  // W^T single-rounded bf16
__device__ __align__(16) unsigned short g_ghi[32 * FEAT];     // gate W^T hi (24 real cols)
__device__ __align__(16) unsigned short g_glo[32 * FEAT];     // gate W^T lo
__device__ __align__(16) float          g_gate[BATCH * 32];   // gate logits (+bias)
__device__ __align__(16) __half         g_exp[BATCH * NCOLS];

// ---------------- helpers ----------------
__device__ __forceinline__ u64 pack2(float lo, float hi) {
    u64 d;
    asm("mov.b64 %0, {%1, %2};" : "=l"(d)
        : "r"(__float_as_uint(lo)), "r"(__float_as_uint(hi)));
    return d;
}
__device__ __forceinline__ void unpack2(u64 v, float &lo, float &hi) {
    unsigned a, b;
    asm("mov.b64 {%0, %1}, %2;" : "=r"(a), "=r"(b) : "l"(v));
    lo = __uint_as_float(a); hi = __uint_as_float(b);
}
__device__ __forceinline__ u64 ffma2(u64 a, u64 b, u64 c) {
    u64 d;
    asm("fma.rn.f32x2 %0, %1, %2, %3;" : "=l"(d) : "l"(a), "l"(b), "l"(c));
    return d;
}
__device__ __forceinline__ u32 smem_u32(const void* p) {
    u32 a;
    asm("{ .reg .u64 t; cvta.to.shared.u64 t, %1; cvt.u32.u64 %0, t; }" : "=r"(a) : "l"(p));
    return a;
}
__device__ __forceinline__ void ldsm4(u32 addr, u32 &r0, u32 &r1, u32 &r2, u32 &r3) {
    asm volatile("ldmatrix.sync.aligned.m8n8.x4.shared.b16 {%0,%1,%2,%3}, [%4];"
                 : "=r"(r0), "=r"(r1), "=r"(r2), "=r"(r3) : "r"(addr));
}
__device__ __forceinline__ void mma16816(float* d, const u32* a, const u32* b) {
    asm volatile("mma.sync.aligned.m16n8k16.row.col.f32.bf16.bf16.f32 "
                 "{%0,%1,%2,%3}, {%4,%5,%6,%7}, {%8,%9}, {%0,%1,%2,%3};"
                 : "+f"(d[0]), "+f"(d[1]), "+f"(d[2]), "+f"(d[3])
                 : "r"(a[0]), "r"(a[1]), "r"(a[2]), "r"(a[3]), "r"(b[0]), "r"(b[1]));
}
#define CP16(dst, src) \
    asm volatile("cp.async.cg.shared.global [%0], [%1], 16;" :: "r"(dst), "l"(src) : "memory")
#define CP_COMMIT() asm volatile("cp.async.commit_group;" ::: "memory")
#define CP_WAIT1()  asm volatile("cp.async.wait_group 1;" ::: "memory")
#define CP_WAIT0()  asm volatile("cp.async.wait_group 0;" ::: "memory")

// ---------------------------------------------------------------------------
// Kernel A: embedding gather + sum (bf16 hi/lo) + fused weight prep.
// ---------------------------------------------------------------------------
__global__ __launch_bounds__(256) void gather_kernel(const int* __restrict__ ids32,
                                                     const float4* __restrict__ emb,
                                                     const float* __restrict__ ew,
                                                     const float* __restrict__ gwp) {
    if (blockIdx.x >= 2560) {
        int wpidx = (blockIdx.x - 2560) * 256 + threadIdx.x;
        if (wpidx < NCOLS * FEAT) {
            int c = wpidx & (NCOLS - 1);
            int k = wpidx >> 9;
            int e = c >> 6, s = c & 63;
            float w = ew[((long)e * FEAT + k) * SS + s];
            __nv_bfloat16 h = __float2bfloat16_rn(w);
            g_whi[(long)c * FEAT + k] = *(unsigned short*)&h;
        } else if (wpidx < NCOLS * FEAT + 32 * FEAT) {
            int gidx = wpidx - NCOLS * FEAT;
            int c = gidx & 31;
            int k = gidx >> 5;
            float w = 0.f;
            if (c < 24) {
                int g = c >> 3, e = c & 7;
                w = gwp[((long)g * FEAT + k) * NE + e];
            }
            __nv_bfloat16 h = __float2bfloat16_rn(w);
            float r = w - __bfloat162float(h);
            __nv_bfloat16 l = __float2bfloat16_rn(r);
            g_ghi[(long)c * FEAT + k] = *(unsigned short*)&h;
            g_glo[(long)c * FEAT + k] = *(unsigned short*)&l;
        }
        return;
    }

    __shared__ int s_is64;
    if (threadIdx.x == 0) {
        const unsigned* w = (const unsigned*)ids32;
        s_is64 = (w[1] == 0u && w[3] == 0u && w[5] == 0u && w[7] == 0u) ? 1 : 0;
    }
    __syncthreads();
    const int is64 = s_is64;

    int tid  = threadIdx.x;
    int p    = blockIdx.x * 64 + (tid >> 2);
    int lane = tid & 3;
    int f = p >> 14;
    int b = p & (BATCH - 1);
    long base = (long)p * LL;

    float4 acc = make_float4(0.f, 0.f, 0.f, 0.f);
    if (is64) {
        const ulonglong2* idv = (const ulonglong2*)(ids32 + 2 * base);
        #pragma unroll
        for (int l2 = 0; l2 < 10; l2++) {
            ulonglong2 two = __ldcs(&idv[l2]);
            int id0 = (int)two.x;
            int id1 = (int)two.y;
            float4 v0 = __ldg(&emb[(long)id0 * 4 + lane]);
            float4 v1 = __ldg(&emb[(long)id1 * 4 + lane]);
            acc.x += v0.x + v1.x; acc.y += v0.y + v1.y;
            acc.z += v0.z + v1.z; acc.w += v0.w + v1.w;
        }
    } else {
        const int4* idv = (const int4*)(ids32 + base);
        #pragma unroll
        for (int l4 = 0; l4 < 5; l4++) {
            int4 four = __ldcs(&idv[l4]);
            float4 v0 = __ldg(&emb[(long)four.x * 4 + lane]);
            float4 v1 = __ldg(&emb[(long)four.y * 4 + lane]);
            float4 v2 = __ldg(&emb[(long)four.z * 4 + lane]);
            float4 v3 = __ldg(&emb[(long)four.w * 4 + lane]);
            acc.x += (v0.x + v1.x) + (v2.x + v3.x);
            acc.y += (v0.y + v1.y) + (v2.y + v3.y);
            acc.z += (v0.z + v1.z) + (v2.z + v3.z);
            acc.w += (v0.w + v1.w) + (v2.w + v3.w);
        }
    }
    int fb = f * DD + lane * 4;
    long xoff = (long)b * FEAT + fb;

    float vals[4] = {acc.x, acc.y, acc.z, acc.w};
    unsigned short hi[4], lo[4];
    #pragma unroll
    for (int j = 0; j < 4; j++) {
        __nv_bfloat16 h = __float2bfloat16_rn(vals[j]);
        float r = vals[j] - __bfloat162float(h);
        __nv_bfloat16 l = __float2bfloat16_rn(r);
        hi[j] = *(unsigned short*)&h;
        lo[j] = *(unsigned short*)&l;
    }
    *(uint2*)&g_xhi[xoff] = make_uint2((u32)hi[0] | ((u32)hi[1] << 16),
                                       (u32)hi[2] | ((u32)hi[3] << 16));
    *(uint2*)&g_xlo[xoff] = make_uint2((u32)lo[0] | ((u32)lo[1] << 16),
                                       (u32)lo[2] | ((u32)lo[3] << 16));
}

// ---------------------------------------------------------------------------
// Kernel B: experts GEMM (1-term bf16, full-K-resident SMEM, single sync)
//           + gates GEMM (3-term, staged pipeline, blockIdx.y==4).
// ---------------------------------------------------------------------------
__device__ __forceinline__ void fill_gate_stage(u32 smb, int stage, int ks,
                                                int b0, int tid) {
    int k0 = ks * 32;
    #pragma unroll
    for (int it = 0; it < 5; it++) {
        int idx = tid + it * 256;           // < 1280
        if (idx < 1024) {
            int tile = idx >> 9;            // 0: xhi, 1: xlo
            int r    = (idx >> 2) & 127;
            int ch   = idx & 3;
            u32 dst = smb + (u32)(((stage * 3 + tile) * STILE_U16 + r * SSTRIDE + ch * 8) * 2);
            const unsigned short* src = (tile == 0)
                ? &g_xhi[(long)(b0 + r) * FEAT + k0 + ch * 8]
                : &g_xlo[(long)(b0 + r) * FEAT + k0 + ch * 8];
            CP16(dst, src);
        } else {
            int idx2 = idx - 1024;          // < 256
            int half = idx2 >> 7;           // 0: ghi, 1: glo
            int r    = (idx2 >> 2) & 31;
            int ch   = idx2 & 3;
            u32 dst = smb + (u32)(((stage * 3 + 2) * STILE_U16
                                   + (half * 32 + r) * SSTRIDE + ch * 8) * 2);
            const unsigned short* src = half
                ? &g_glo[(long)r * FEAT + k0 + ch * 8]
                : &g_ghi[(long)r * FEAT + k0 + ch * 8];
            CP16(dst, src);
        }
    }
}

__global__ void __launch_bounds__(256, 2) expert_mma_kernel(const float* __restrict__ eb,
                                                            const float* __restrict__ gb) {
    extern __shared__ unsigned short sm16[];
    __shared__ float s_bias[TN];

    int tid  = threadIdx.x;
    int wid  = tid >> 5;
    int lane = tid & 31;
    int b0   = blockIdx.x * TM;

    u32 smb = smem_u32(sm16);

    if (blockIdx.y == 4) {
        // ---- gates: 128 rows x 32 cols (24 real), 3-term split, staged ----
        if (tid < 32) s_bias[tid] = (tid < 24) ? gb[tid] : 0.f;

        fill_gate_stage(smb, 0, 0, b0, tid); CP_COMMIT();
        fill_gate_stage(smb, 1, 1, b0, tid); CP_COMMIT();

        int m0 = wid * 16;
        u32 aOff = (u32)((m0 + (lane & 15)) * SSTRIDE + ((lane & 16) ? 8 : 0)) * 2;
        u32 bOff = (u32)(((lane & 7) + ((lane & 16) ? 8 : 0)) * SSTRIDE + ((lane & 8) ? 8 : 0)) * 2;

        float acc[4][4];
        #pragma unroll
        for (int nt = 0; nt < 4; nt++)
            #pragma unroll
            for (int q = 0; q < 4; q++) acc[nt][q] = 0.f;

        #pragma unroll 1
        for (int ks = 0; ks < 5; ks++) {
            if (ks < 4) CP_WAIT1(); else CP_WAIT0();
            __syncthreads();

            int stage = ks & 1;
            u32 aHiB = smb + (u32)((stage * 3 + 0) * STILE_U16 * 2) + aOff;
            u32 aLoB = smb + (u32)((stage * 3 + 1) * STILE_U16 * 2) + aOff;
            u32 bHiB = smb + (u32)((stage * 3 + 2) * STILE_U16 * 2) + bOff;
            u32 bLoB = bHiB + (u32)(32 * SSTRIDE * 2);

            #pragma unroll
            for (int kk = 0; kk < 2; kk++) {
                u32 kb = (u32)(kk * 32);
                u32 ah[4], al[4];
                ldsm4(aHiB + kb, ah[0], ah[1], ah[2], ah[3]);
                ldsm4(aLoB + kb, al[0], al[1], al[2], al[3]);
                u32 bh[2][4], blo[2][4];
                #pragma unroll
                for (int nt2 = 0; nt2 < 2; nt2++) {
                    u32 noff = (u32)(nt2 * 16 * SSTRIDE * 2);
                    ldsm4(bHiB + noff + kb, bh[nt2][0], bh[nt2][1], bh[nt2][2], bh[nt2][3]);
                    ldsm4(bLoB + noff + kb, blo[nt2][0], blo[nt2][1], blo[nt2][2], blo[nt2][3]);
                }
                #pragma unroll
                for (int nt2 = 0; nt2 < 2; nt2++) {
                    mma16816(acc[2 * nt2],     ah, &bh[nt2][0]);
                    mma16816(acc[2 * nt2 + 1], ah, &bh[nt2][2]);
                    mma16816(acc[2 * nt2],     ah, &blo[nt2][0]);
                    mma16816(acc[2 * nt2 + 1], ah, &blo[nt2][2]);
                    mma16816(acc[2 * nt2],     al, &bh[nt2][0]);
                    mma16816(acc[2 * nt2 + 1], al, &bh[nt2][2]);
                }
            }

            __syncthreads();
            if (ks + 2 < 5) { fill_gate_stage(smb, ks & 1, ks + 2, b0, tid); CP_COMMIT(); }
        }

        int r0 = b0 + m0 + (lane >> 2);
        #pragma unroll
        for (int nt = 0; nt < 3; nt++) {
            int cl = nt * 8 + (lane & 3) * 2;
            float bi0 = s_bias[cl], bi1 = s_bias[cl + 1];
            g_gate[(long)r0 * 32 + cl]           = acc[nt][0] + bi0;
            g_gate[(long)r0 * 32 + cl + 1]       = acc[nt][1] + bi1;
            g_gate[(long)(r0 + 8) * 32 + cl]     = acc[nt][2] + bi0;
            g_gate[(long)(r0 + 8) * 32 + cl + 1] = acc[nt][3] + bi1;
        }
        return;
    }

    // ---- experts path: 1-term bf16, full K resident, one fill + one sync ----
    int c0 = blockIdx.y * TN;
    if (tid < TN) {
        int c = c0 + tid;
        s_bias[tid] = eb[(c >> 6) * SS + (c & 63)];
    }

    #pragma unroll
    for (int it = 0; it < 20; it++) {
        int idx  = tid + it * 256;          // < 5120
        int half = idx >= 2560;             // 0: xhi, 1: whi
        int rem  = half ? idx - 2560 : idx; // < 2560
        int c    = rem >> 9;                // chunk 0..4
        int sub  = rem & 511;
        int r    = sub >> 2;
        int ch   = sub & 3;
        int k0   = c * 32;
        u32 dst = smb + (u32)(((half * 5 + c) * STILE_U16 + r * SSTRIDE + ch * 8) * 2);
        const unsigned short* src = half
            ? &g_whi[(long)(c0 + r) * FEAT + k0 + ch * 8]
            : &g_xhi[(long)(b0 + r) * FEAT + k0 + ch * 8];
        CP16(dst, src);
    }
    CP_COMMIT();
    CP_WAIT0();
    __syncthreads();

    int m0 = (wid >> 1) * 32;
    int n0 = (wid & 1) * 64;

    u32 aOff = (u32)((m0 + (lane & 15)) * SSTRIDE + ((lane & 16) ? 8 : 0)) * 2;
    u32 bOff = (u32)((n0 + (lane & 7) + ((lane & 16) ? 8 : 0)) * SSTRIDE + ((lane & 8) ? 8 : 0)) * 2;

    float acc[2][8][4];
    #pragma unroll
    for (int mt = 0; mt < 2; mt++)
        #pragma unroll
        for (int nt = 0; nt < 8; nt++)
            #pragma unroll
            for (int q = 0; q < 4; q++) acc[mt][nt][q] = 0.f;

    #pragma unroll
    for (int c = 0; c < 5; c++) {
        u32 aHiB = smb + (u32)(c * STILE_U16 * 2) + aOff;
        u32 bHiB = smb + (u32)((5 + c) * STILE_U16 * 2) + bOff;

        #pragma unroll
        for (int kk = 0; kk < 2; kk++) {
            u32 kb = (u32)(kk * 32);

            u32 ah[2][4];
            #pragma unroll
            for (int mt = 0; mt < 2; mt++) {
                u32 moff = (u32)(mt * 16 * SSTRIDE * 2);
                ldsm4(aHiB + moff + kb, ah[mt][0], ah[mt][1], ah[mt][2], ah[mt][3]);
            }
            u32 bh[4][4];
            #pragma unroll
            for (int nt2 = 0; nt2 < 4; nt2++) {
                u32 noff = (u32)(nt2 * 16 * SSTRIDE * 2);
                ldsm4(bHiB + noff + kb, bh[nt2][0], bh[nt2][1], bh[nt2][2], bh[nt2][3]);
            }

            #pragma unroll
            for (int mt = 0; mt < 2; mt++) {
                #pragma unroll
                for (int nt2 = 0; nt2 < 4; nt2++) {
                    mma16816(acc[mt][2 * nt2],     ah[mt], &bh[nt2][0]);
                    mma16816(acc[mt][2 * nt2 + 1], ah[mt], &bh[nt2][2]);
                }
            }
        }
    }

    #pragma unroll
    for (int mt = 0; mt < 2; mt++) {
        int row = b0 + m0 + mt * 16 + (lane >> 2);
        #pragma unroll
        for (int nt = 0; nt < 8; nt++) {
            int cl = n0 + nt * 8 + (lane & 3) * 2;
            float bi0 = s_bias[cl], bi1 = s_bias[cl + 1];
            float* d = acc[mt][nt];
            *(__half2*)&g_exp[(long)row * NCOLS + c0 + cl] =
                __floats2half2_rn(fmaxf(d[0] + bi0, 0.f), fmaxf(d[1] + bi1, 0.f));
            *(__half2*)&g_exp[(long)(row + 8) * NCOLS + c0 + cl] =
                __floats2half2_rn(fmaxf(d[2] + bi0, 0.f), fmaxf(d[3] + bi1, 0.f));
        }
    }
}

// ---------------------------------------------------------------------------
// Kernel C: head, warp-per-2-rows, 4 row-pair iterations per warp (grid 256).
// ---------------------------------------------------------------------------
struct HeadSmem {
    ulonglong2 tw4[16][96];
    float mix[8][2][192];
    float ow0[NG * TT];
    float ow1[NG * TT];
    float tb[NG * TT];
    float ob[8];
};

__global__ __launch_bounds__(256) void head_kernel(const float* __restrict__ tw,
                                                   const float* __restrict__ tb,
                                                   const float* __restrict__ ow,
                                                   const float* __restrict__ ob,
                                                   float* __restrict__ out) {
    extern __shared__ char smem_raw[];
    HeadSmem* sm = (HeadSmem*)smem_raw;

    int tid  = threadIdx.x;
    int warp = tid >> 5;
    int lane = tid & 31;

    for (int i = tid; i < 16 * 96; i += 256) {
        int sp2 = i / 96, j = i % 96;
        int g = j >> 5, t = j & 31;
        int s0 = 4 * sp2;
        float v0 = tw[((long)g * SS + s0 + 0) * TT + t];
        float v1 = tw[((long)g * SS + s0 + 1) * TT + t];
        float v2 = tw[((long)g * SS + s0 + 2) * TT + t];
        float v3 = tw[((long)g * SS + s0 + 3) * TT + t];
        ulonglong2 v;
        v.x = pack2(v0, v1);
        v.y = pack2(v2, v3);
        sm->tw4[sp2][j] = v;
    }
    for (int i = tid; i < NG * TT; i += 256) {
        sm->ow0[i] = ow[i * 2 + 0];
        sm->ow1[i] = ow[i * 2 + 1];
        sm->tb[i]  = tb[i];
    }
    if (tid < NG * 2) sm->ob[tid] = ob[tid];
    __syncthreads();

    #pragma unroll 1
    for (int it = 0; it < 4; it++) {
        int bA = blockIdx.x * 8 + warp + it * 2048;
        int bB = bA + 8192;

        __syncwarp();

        int oSafe = (lane < 24) ? lane : 0;
        float lgA = g_gate[(long)bA * 32 + oSafe];
        float lgB = g_gate[(long)bB * 32 + oSafe];
        float gvA, gvB;
        {
            float mA = lgA, mB = lgB;
            #pragma unroll
            for (int b = 1; b <= 4; b <<= 1) {
                mA = fmaxf(mA, __shfl_xor_sync(0xFFFFFFFFu, mA, b));
                mB = fmaxf(mB, __shfl_xor_sync(0xFFFFFFFFu, mB, b));
            }
            float eA = __expf(lgA - mA);
            float eB = __expf(lgB - mB);
            float sA = eA, sB = eB;
            #pragma unroll
            for (int b = 1; b <= 4; b <<= 1) {
                sA += __shfl_xor_sync(0xFFFFFFFFu, sA, b);
                sB += __shfl_xor_sync(0xFFFFFFFFu, sB, b);
            }
            gvA = eA * __fdividef(1.f, sA);
            gvB = eB * __fdividef(1.f, sB);
        }
        float gtA[24], gtB[24];
        #pragma unroll
        for (int o = 0; o < 24; o++) {
            gtA[o] = __shfl_sync(0xFFFFFFFFu, gvA, o);
            gtB[o] = __shfl_sync(0xFFFFFFFFu, gvB, o);
        }

        const __half2* erA = (const __half2*)&g_exp[(long)bA * NCOLS];
        const __half2* erB = (const __half2*)&g_exp[(long)bB * NCOLS];
        #pragma unroll
        for (int g = 0; g < NG; g++) {
            float vA0 = 0.f, vA1 = 0.f, vB0 = 0.f, vB1 = 0.f;
            #pragma unroll
            for (int e = 0; e < NE; e++) {
                float2 fa = __half22float2(erA[e * (SS / 2) + lane]);
                float2 fb = __half22float2(erB[e * (SS / 2) + lane]);
                float ga = gtA[g * 8 + e], gbv = gtB[g * 8 + e];
                vA0 = fmaf(ga, fa.x, vA0);
                vA1 = fmaf(ga, fa.y, vA1);
                vB0 = fmaf(gbv, fb.x, vB0);
                vB1 = fmaf(gbv, fb.y, vB1);
            }
            *(float2*)&sm->mix[warp][0][g * SS + 2 * lane] = make_float2(vA0, vA1);
            *(float2*)&sm->mix[warp][1][g * SS + 2 * lane] = make_float2(vB0, vB1);
        }
        __syncwarp();

        float towA[NG], towB[NG];
        #pragma unroll
        for (int g = 0; g < NG; g++) {
            u64 accA = 0ull, accB = 0ull;
            const ulonglong2* mA = (const ulonglong2*)&sm->mix[warp][0][g * SS];
            const ulonglong2* mB = (const ulonglong2*)&sm->mix[warp][1][g * SS];
            #pragma unroll
            for (int sp2 = 0; sp2 < 16; sp2++) {
                ulonglong2 w  = sm->tw4[sp2][g * 32 + lane];
                ulonglong2 ma = mA[sp2];
                ulonglong2 mb = mB[sp2];
                accA = ffma2(ma.x, w.x, accA);
                accA = ffma2(ma.y, w.y, accA);
                accB = ffma2(mb.x, w.x, accB);
                accB = ffma2(mb.y, w.y, accB);
            }
            float l0, h0, l1, h1;
            unpack2(accA, l0, h0);
            unpack2(accB, l1, h1);
            float bias = sm->tb[g * TT + lane];
            towA[g] = fmaxf(l0 + h0 + bias, 0.f);
            towB[g] = fmaxf(l1 + h1 + bias, 0.f);
        }

        float lA[6], lB[6];
        #pragma unroll
        for (int g = 0; g < NG; g++) {
            lA[g * 2 + 0] = towA[g] * sm->ow0[g * TT + lane];
            lA[g * 2 + 1] = towA[g] * sm->ow1[g * TT + lane];
            lB[g * 2 + 0] = towB[g] * sm->ow0[g * TT + lane];
            lB[g * 2 + 1] = towB[g] * sm->ow1[g * TT + lane];
        }
        #pragma unroll
        for (int off = 16; off > 0; off >>= 1) {
            #pragma unroll
            for (int o = 0; o < 6; o++) {
                lA[o] += __shfl_xor_sync(0xFFFFFFFFu, lA[o], off);
                lB[o] += __shfl_xor_sync(0xFFFFFFFFu, lB[o], off);
            }
        }

        if (lane < 2) {
            const float* l = (lane == 0) ? lA : lB;
            int b = (lane == 0) ? bA : bB;
            float probs[6];
            #pragma unroll
            for (int g = 0; g < NG; g++) {
                float l0 = l[g * 2 + 0] + sm->ob[g * 2 + 0];
                float l1 = l[g * 2 + 1] + sm->ob[g * 2 + 1];
                float mm = fmaxf(l0, l1);
                float e0 = __expf(l0 - mm), e1 = __expf(l1 - mm);
                float inv = __fdividef(1.f, e0 + e1);
                probs[g * 2 + 0] = fminf(fmaxf(e0 * inv, 1e-15f), 1.f - 1e-15f);
                probs[g * 2 + 1] = fminf(fmaxf(e1 * inv, 1e-15f), 1.f - 1e-15f);
            }
            float cc = probs[1] * probs[3];
            float* o = out + (long)b * 10;
            o[0] = probs[0]; o[1] = probs[1]; o[2] = probs[1];
            o[3] = probs[2]; o[4] = probs[3]; o[5] = probs[3];
            o[6] = 1.f - cc; o[7] = cc; o[8] = cc;
            o[9] = probs[5];
        }
    }
}

extern "C" void kernel_launch(void* const* d_in, const int* in_sizes, int n_in,
                              void* d_out, int out_size) {
    const int*   ids = (const int*)d_in[0];
    const float* emb = (const float*)d_in[1];
    const float* ew  = (const float*)d_in[2];
    const float* eb  = (const float*)d_in[3];
    const float* gw  = (const float*)d_in[4];
    const float* gb  = (const float*)d_in[5];
    const float* tw  = (const float*)d_in[6];
    const float* tb  = (const float*)d_in[7];
    const float* ow  = (const float*)d_in[8];
    const float* ob  = (const float*)d_in[9];
    float* out = (float*)d_out;

    cudaFuncSetAttribute(expert_mma_kernel, cudaFuncAttributeMaxDynamicSharedMemorySize, DYN_E);
    cudaFuncSetAttribute(head_kernel, cudaFuncAttributeMaxDynamicSharedMemorySize,
                         (int)sizeof(HeadSmem));

    gather_kernel<<<2560 + 340, 256>>>(ids, (const float4*)emb, ew, gw);
    expert_mma_kernel<<<dim3(BATCH / TM, 5), 256, DYN_E>>>(eb, gb);
    head_kernel<<<256, 256, sizeof(HeadSmem)>>>(tw, tb, ow, ob, out);
}